// round 1
// baseline (speedup 1.0000x reference)
#include <cuda_runtime.h>
#include <math.h>

// Problem constants
#define BB     4
#define LL     2048
#define DMODEL 1024
#define EI     2048      // d_inner
#define NSTATE 16
#define DCONV  4
#define DTRANK 64
#define DFF    4096
#define MROWS  (BB*LL)           // 8192
#define XDBLW  (DTRANK+2*NSTATE) // 96

// -------- scratch (device globals; no allocation allowed) --------
__device__ float g_xz  [(size_t)MROWS*2*EI];   // in_proj out: u | z   (128MB)
__device__ float g_uc  [(size_t)MROWS*EI];     // conv+silu out        (64MB)
__device__ float g_xdbl[(size_t)MROWS*XDBLW];  // dt_raw | B | C       (3MB)
__device__ float g_dt  [(size_t)MROWS*EI];     // softplus(dt)         (64MB)
__device__ float g_y   [(size_t)MROWS*EI];     // scan out * silu(z)   (64MB)
__device__ float g_y2  [(size_t)MROWS*DMODEL]; // out_proj out         (32MB)
__device__ float g_hh  [(size_t)MROWS*DFF];    // ffn hidden           (128MB)

// ---------------- generic tiled SGEMM: C[M,N] = A[M,K] * W[N,K]^T ----------------
// EPI: 0=none, 1=bias+relu, 2=bias, 3=bias+softplus
template<int EPI>
__global__ void __launch_bounds__(256)
sgemm_nt(const float* __restrict__ A, int lda,
         const float* __restrict__ W,
         const float* __restrict__ bias,
         float* __restrict__ C,
         int Nv, int Kv)
{
    __shared__ float As[8][128];
    __shared__ float Ws[8][128];
    const int tid = threadIdx.x;
    const int bm = blockIdx.y * 128, bn = blockIdx.x * 128;
    const int tr = tid >> 4, tc = tid & 15;
    const int lr = tid >> 1, lc = (tid & 1) * 4;

    float acc[8][8];
#pragma unroll
    for (int i = 0; i < 8; i++)
#pragma unroll
        for (int j = 0; j < 8; j++) acc[i][j] = 0.f;

    for (int k0 = 0; k0 < Kv; k0 += 8) {
        float4 av = *(const float4*)(A + (size_t)(bm + lr) * lda + k0 + lc);
        float4 wv = make_float4(0.f, 0.f, 0.f, 0.f);
        if (bn + lr < Nv)
            wv = *(const float4*)(W + (size_t)(bn + lr) * Kv + k0 + lc);
        As[lc + 0][lr] = av.x; As[lc + 1][lr] = av.y;
        As[lc + 2][lr] = av.z; As[lc + 3][lr] = av.w;
        Ws[lc + 0][lr] = wv.x; Ws[lc + 1][lr] = wv.y;
        Ws[lc + 2][lr] = wv.z; Ws[lc + 3][lr] = wv.w;
        __syncthreads();
#pragma unroll
        for (int kk = 0; kk < 8; kk++) {
            float4 a0 = *(const float4*)&As[kk][tr * 4];
            float4 a1 = *(const float4*)&As[kk][64 + tr * 4];
            float4 w0 = *(const float4*)&Ws[kk][tc * 4];
            float4 w1 = *(const float4*)&Ws[kk][64 + tc * 4];
            float a[8] = {a0.x, a0.y, a0.z, a0.w, a1.x, a1.y, a1.z, a1.w};
            float w[8] = {w0.x, w0.y, w0.z, w0.w, w1.x, w1.y, w1.z, w1.w};
#pragma unroll
            for (int i = 0; i < 8; i++)
#pragma unroll
                for (int j = 0; j < 8; j++) acc[i][j] += a[i] * w[j];
        }
        __syncthreads();
    }

#pragma unroll
    for (int i = 0; i < 8; i++) {
        int m = bm + (i < 4 ? tr * 4 + i : 64 + tr * 4 + (i - 4));
#pragma unroll
        for (int j = 0; j < 8; j++) {
            int n = bn + (j < 4 ? tc * 4 + j : 64 + tc * 4 + (j - 4));
            if (n < Nv) {
                float v = acc[i][j];
                if (EPI == 1)      v = fmaxf(v + bias[n], 0.f);
                else if (EPI == 2) v = v + bias[n];
                else if (EPI == 3) { v += bias[n]; v = (v > 20.f) ? v : log1pf(expf(v)); }
                C[(size_t)m * Nv + n] = v;
            }
        }
    }
}

// ---------------- causal depthwise conv (k=4) + bias + silu ----------------
__global__ void conv_silu_kernel(const float* __restrict__ conv_w,
                                 const float* __restrict__ conv_b)
{
    size_t idx = (size_t)blockIdx.x * blockDim.x + threadIdx.x;
    if (idx >= (size_t)MROWS * EI) return;
    int e = (int)(idx % EI);
    int row = (int)(idx / EI);   // b*L + l
    int l = row % LL;
    float s = conv_b[e];
#pragma unroll
    for (int j = 0; j < DCONV; j++) {
        int ls = l - (DCONV - 1) + j;
        if (ls >= 0) {
            int rs = row - (DCONV - 1) + j;
            s += conv_w[e * DCONV + j] * g_xz[(size_t)rs * (2 * EI) + e];
        }
    }
    float sig = 1.f / (1.f + expf(-s));
    g_uc[idx] = s * sig;
}

// ---------------- selective scan: 16 lanes per (b,e) channel ----------------
__global__ void scan_kernel(const float* __restrict__ A_log,
                            const float* __restrict__ Dp)
{
    int gid = blockIdx.x * (blockDim.x >> 4) + (threadIdx.x >> 4); // channel: b*EI+e
    int n = threadIdx.x & 15;
    int b = gid >> 11;          // EI = 2048
    int e = gid & (EI - 1);

    float Aen = -expf(A_log[e * NSTATE + n]);
    float Dv = Dp[e];
    float h = 0.f;
    size_t row = (size_t)b * LL;
    for (int l = 0; l < LL; l++, row++) {
        float dtv = g_dt[row * EI + e];
        float uv  = g_uc[row * EI + e];
        const float* pbc = g_xdbl + row * XDBLW;
        float Bt = pbc[DTRANK + n];
        float Ct = pbc[DTRANK + NSTATE + n];
        h = expf(dtv * Aen) * h + dtv * uv * Bt;
        float p = h * Ct;
        p += __shfl_xor_sync(0xffffffffu, p, 8);
        p += __shfl_xor_sync(0xffffffffu, p, 4);
        p += __shfl_xor_sync(0xffffffffu, p, 2);
        p += __shfl_xor_sync(0xffffffffu, p, 1);
        if (n == 0) {
            float zv = g_xz[row * (2 * EI) + EI + e];
            float yv = (p + uv * Dv) * (zv / (1.f + expf(-zv)));
            g_y[row * EI + e] = yv;
        }
    }
}

// ---------------- host launch ----------------
extern "C" void kernel_launch(void* const* d_in, const int* in_sizes, int n_in,
                              void* d_out, int out_size)
{
    const float* x          = (const float*)d_in[0];
    const float* in_proj_w  = (const float*)d_in[1];
    const float* conv_w     = (const float*)d_in[2];
    const float* conv_b     = (const float*)d_in[3];
    const float* x_proj_w   = (const float*)d_in[4];
    const float* dt_proj_w  = (const float*)d_in[5];
    const float* dt_proj_b  = (const float*)d_in[6];
    const float* A_log      = (const float*)d_in[7];
    const float* Dp         = (const float*)d_in[8];
    const float* out_proj_w = (const float*)d_in[9];
    const float* lin1_w     = (const float*)d_in[10];
    const float* lin1_b     = (const float*)d_in[11];
    const float* lin2_w     = (const float*)d_in[12];
    const float* lin2_b     = (const float*)d_in[13];
    float* out = (float*)d_out;

    float *p_xz, *p_uc, *p_xdbl, *p_dt, *p_y, *p_y2, *p_h;
    cudaGetSymbolAddress((void**)&p_xz,   g_xz);
    cudaGetSymbolAddress((void**)&p_uc,   g_uc);
    cudaGetSymbolAddress((void**)&p_xdbl, g_xdbl);
    cudaGetSymbolAddress((void**)&p_dt,   g_dt);
    cudaGetSymbolAddress((void**)&p_y,    g_y);
    cudaGetSymbolAddress((void**)&p_y2,   g_y2);
    cudaGetSymbolAddress((void**)&p_h,    g_hh);

    dim3 blk(256);

    // 1) xz = x @ in_proj_w^T            [8192,1024]x[4096,1024] -> [8192,4096]
    sgemm_nt<0><<<dim3((2 * EI) / 128, MROWS / 128), blk>>>(
        x, DMODEL, in_proj_w, nullptr, p_xz, 2 * EI, DMODEL);

    // 2) causal depthwise conv + silu -> g_uc
    conv_silu_kernel<<<(unsigned)(((size_t)MROWS * EI) / 256), 256>>>(conv_w, conv_b);

    // 3) x_dbl = uc @ x_proj_w^T         [8192,2048]x[96,2048] -> [8192,96]
    sgemm_nt<0><<<dim3((XDBLW + 127) / 128, MROWS / 128), blk>>>(
        p_uc, EI, x_proj_w, nullptr, p_xdbl, XDBLW, EI);

    // 4) dt = softplus(dt_raw @ dt_proj_w^T + b)  [8192,64]x[2048,64] -> [8192,2048]
    sgemm_nt<3><<<dim3(EI / 128, MROWS / 128), blk>>>(
        p_xdbl, XDBLW, dt_proj_w, dt_proj_b, p_dt, EI, DTRANK);

    // 5) selective scan (+ u*D, * silu(z)) -> g_y
    scan_kernel<<<(BB * EI) / 16, 256>>>(A_log, Dp);

    // 6) y2 = y @ out_proj_w^T           [8192,2048]x[1024,2048] -> [8192,1024]
    sgemm_nt<0><<<dim3(DMODEL / 128, MROWS / 128), blk>>>(
        p_y, EI, out_proj_w, nullptr, p_y2, DMODEL, EI);

    // 7) h = relu(y2 @ lin1_w^T + b)     [8192,1024]x[4096,1024] -> [8192,4096]
    sgemm_nt<1><<<dim3(DFF / 128, MROWS / 128), blk>>>(
        p_y2, DMODEL, lin1_w, lin1_b, p_h, DFF, DMODEL);

    // 8) out = h @ lin2_w^T + b          [8192,4096]x[1024,4096] -> [8192,1024]
    sgemm_nt<2><<<dim3(DMODEL / 128, MROWS / 128), blk>>>(
        p_h, DFF, lin2_w, lin2_b, out, DMODEL, DFF);
}

// round 5
// speedup vs baseline: 1.3344x; 1.3344x over previous
#include <cuda_runtime.h>
#include <cuda_bf16.h>
#include <stdint.h>
#include <math.h>

// Problem constants
#define BB     4
#define LL     2048
#define DMODEL 1024
#define EI     2048      // d_inner
#define NSTATE 16
#define DCONV  4
#define DTRANK 64
#define DFF    4096
#define MROWS  (BB*LL)           // 8192
#define XDBLW  (DTRANK+2*NSTATE) // 96

// -------- scratch (device globals; no allocation allowed) --------
__device__ float g_xz  [(size_t)MROWS*2*EI];
__device__ float g_uc  [(size_t)MROWS*EI];
__device__ float g_xdbl[(size_t)MROWS*XDBLW];
__device__ float g_dt  [(size_t)MROWS*EI];
__device__ float g_y   [(size_t)MROWS*EI];
__device__ float g_y2  [(size_t)MROWS*DMODEL];
__device__ float g_hh  [(size_t)MROWS*DFF];

// ---------------- PTX helpers ----------------
__device__ __forceinline__ void ldsm4(unsigned& r0, unsigned& r1, unsigned& r2, unsigned& r3,
                                      const void* p)
{
    unsigned a = (unsigned)__cvta_generic_to_shared(p);
    asm volatile("ldmatrix.sync.aligned.m8n8.x4.shared.b16 {%0,%1,%2,%3}, [%4];\n"
                 : "=r"(r0), "=r"(r1), "=r"(r2), "=r"(r3) : "r"(a));
}

__device__ __forceinline__ void mma16816(float* d, const unsigned* a, const unsigned* b)
{
    asm volatile(
        "mma.sync.aligned.m16n8k16.row.col.f32.bf16.bf16.f32 "
        "{%0,%1,%2,%3}, {%4,%5,%6,%7}, {%8,%9}, {%0,%1,%2,%3};\n"
        : "+f"(d[0]), "+f"(d[1]), "+f"(d[2]), "+f"(d[3])
        : "r"(a[0]), "r"(a[1]), "r"(a[2]), "r"(a[3]), "r"(b[0]), "r"(b[1]));
}

template<int EPI>
__device__ __forceinline__ float epi_apply(float v, const float* bias, int n)
{
    if (EPI == 1)      v = fmaxf(v + bias[n], 0.f);
    else if (EPI == 2) v = v + bias[n];
    else if (EPI == 3) { v += bias[n]; v = (v > 20.f) ? v : log1pf(expf(v)); }
    return v;
}

// ------------- bf16x3 tensor-core GEMM: C[M,N] = A[M,K] * W[N,K]^T -------------
// EPI: 0=none, 1=bias+relu, 2=bias, 3=bias+softplus
#define SKW 40   // smem row stride in bf16 elements (padding for conflict-free LDSM)
template<int EPI>
__global__ void __launch_bounds__(256)
gemm_bf16x3(const float* __restrict__ A, int lda,
            const float* __restrict__ W,
            const float* __restrict__ bias,
            float* __restrict__ C,
            int Nv, int Kv)
{
    __shared__ __nv_bfloat16 sAhi[128][SKW];
    __shared__ __nv_bfloat16 sAlo[128][SKW];
    __shared__ __nv_bfloat16 sWhi[128][SKW];
    __shared__ __nv_bfloat16 sWlo[128][SKW];

    const int tid  = threadIdx.x;
    const int bm   = blockIdx.y * 128;
    const int bn   = blockIdx.x * 128;
    const int lane = tid & 31;
    const int w    = tid >> 5;
    const int wm   = (w >> 1) * 32;     // warp tile: 32 rows
    const int wn   = (w & 1) * 64;      // warp tile: 64 cols

    const int lrow = tid >> 3;          // 0..31 (load mapping)
    const int lcol = (tid & 7) * 4;     // 0..28 step 4

    float acc[2][8][4];
#pragma unroll
    for (int i = 0; i < 2; i++)
#pragma unroll
        for (int j = 0; j < 8; j++)
#pragma unroll
            for (int q = 0; q < 4; q++) acc[i][j][q] = 0.f;

    // ldmatrix smem source lane mappings
    const int a_r = lane & 15, a_c = (lane >> 4) * 8;
    const int b_r = (lane & 7) + ((lane >> 4) << 3), b_c = ((lane >> 3) & 1) * 8;

    for (int k0 = 0; k0 < Kv; k0 += 32) {
        // ---- load & split fp32 -> (hi, lo) bf16 ----
#pragma unroll
        for (int i = 0; i < 4; i++) {
            int r = lrow + i * 32;
            float4 av = *(const float4*)(A + (size_t)(bm + r) * lda + k0 + lcol);
            float4 wv = make_float4(0.f, 0.f, 0.f, 0.f);
            if (bn + r < Nv)
                wv = *(const float4*)(W + (size_t)(bn + r) * Kv + k0 + lcol);
            float va[4] = {av.x, av.y, av.z, av.w};
            float vw[4] = {wv.x, wv.y, wv.z, wv.w};
#pragma unroll
            for (int j = 0; j < 4; j++) {
                __nv_bfloat16 h = __float2bfloat16(va[j]);
                sAhi[r][lcol + j] = h;
                sAlo[r][lcol + j] = __float2bfloat16(va[j] - __bfloat162float(h));
                __nv_bfloat16 gq = __float2bfloat16(vw[j]);
                sWhi[r][lcol + j] = gq;
                sWlo[r][lcol + j] = __float2bfloat16(vw[j] - __bfloat162float(gq));
            }
        }
        __syncthreads();

        // ---- 2 k-steps of 16 ----
#pragma unroll
        for (int kk = 0; kk < 32; kk += 16) {
            unsigned ahi[2][4], alo[2][4];
#pragma unroll
            for (int mi = 0; mi < 2; mi++) {
                ldsm4(ahi[mi][0], ahi[mi][1], ahi[mi][2], ahi[mi][3],
                      &sAhi[wm + mi * 16 + a_r][kk + a_c]);
                ldsm4(alo[mi][0], alo[mi][1], alo[mi][2], alo[mi][3],
                      &sAlo[wm + mi * 16 + a_r][kk + a_c]);
            }
#pragma unroll
            for (int p = 0; p < 4; p++) {
                unsigned bh[4], bl[4];
                ldsm4(bh[0], bh[1], bh[2], bh[3], &sWhi[wn + p * 16 + b_r][kk + b_c]);
                ldsm4(bl[0], bl[1], bl[2], bl[3], &sWlo[wn + p * 16 + b_r][kk + b_c]);
#pragma unroll
                for (int mi = 0; mi < 2; mi++) {
                    mma16816(acc[mi][2 * p],     ahi[mi], bh);
                    mma16816(acc[mi][2 * p],     ahi[mi], bl);
                    mma16816(acc[mi][2 * p],     alo[mi], bh);
                    mma16816(acc[mi][2 * p + 1], ahi[mi], bh + 2);
                    mma16816(acc[mi][2 * p + 1], ahi[mi], bl + 2);
                    mma16816(acc[mi][2 * p + 1], alo[mi], bh + 2);
                }
            }
        }
        __syncthreads();
    }

    // ---- epilogue ----
    const int grp = lane >> 2;
    const int tq  = lane & 3;
#pragma unroll
    for (int mi = 0; mi < 2; mi++) {
#pragma unroll
        for (int nj = 0; nj < 8; nj++) {
            int r0 = bm + wm + mi * 16 + grp;
            int c  = bn + wn + nj * 8 + tq * 2;
            if (c < Nv) {
                float* d = acc[mi][nj];
                C[(size_t)r0 * Nv + c]           = epi_apply<EPI>(d[0], bias, c);
                C[(size_t)r0 * Nv + c + 1]       = epi_apply<EPI>(d[1], bias, c + 1);
                C[(size_t)(r0 + 8) * Nv + c]     = epi_apply<EPI>(d[2], bias, c);
                C[(size_t)(r0 + 8) * Nv + c + 1] = epi_apply<EPI>(d[3], bias, c + 1);
            }
        }
    }
}

// ---------------- causal depthwise conv (k=4) + bias + silu ----------------
__global__ void conv_silu_kernel(const float* __restrict__ conv_w,
                                 const float* __restrict__ conv_b)
{
    size_t idx = (size_t)blockIdx.x * blockDim.x + threadIdx.x;
    if (idx >= (size_t)MROWS * EI) return;
    int e = (int)(idx % EI);
    int row = (int)(idx / EI);
    int l = row % LL;
    float s = conv_b[e];
#pragma unroll
    for (int j = 0; j < DCONV; j++) {
        int ls = l - (DCONV - 1) + j;
        if (ls >= 0) {
            int rs = row - (DCONV - 1) + j;
            s += conv_w[e * DCONV + j] * g_xz[(size_t)rs * (2 * EI) + e];
        }
    }
    float sig = 1.f / (1.f + expf(-s));
    g_uc[idx] = s * sig;
}

// ---------------- selective scan: 16 lanes per (b,e) channel ----------------
__global__ void scan_kernel(const float* __restrict__ A_log,
                            const float* __restrict__ Dp)
{
    int gid = blockIdx.x * (blockDim.x >> 4) + (threadIdx.x >> 4);
    int n = threadIdx.x & 15;
    int b = gid >> 11;
    int e = gid & (EI - 1);

    float Aen = -expf(A_log[e * NSTATE + n]);
    float Dv = Dp[e];
    float h = 0.f;
    size_t row = (size_t)b * LL;
    for (int l = 0; l < LL; l++, row++) {
        float dtv = g_dt[row * EI + e];
        float uv  = g_uc[row * EI + e];
        const float* pbc = g_xdbl + row * XDBLW;
        float Bt = pbc[DTRANK + n];
        float Ct = pbc[DTRANK + NSTATE + n];
        h = expf(dtv * Aen) * h + dtv * uv * Bt;
        float p = h * Ct;
        p += __shfl_xor_sync(0xffffffffu, p, 8);
        p += __shfl_xor_sync(0xffffffffu, p, 4);
        p += __shfl_xor_sync(0xffffffffu, p, 2);
        p += __shfl_xor_sync(0xffffffffu, p, 1);
        if (n == 0) {
            float zv = g_xz[row * (2 * EI) + EI + e];
            float yv = (p + uv * Dv) * (zv / (1.f + expf(-zv)));
            g_y[row * EI + e] = yv;
        }
    }
}

// ---------------- host launch ----------------
extern "C" void kernel_launch(void* const* d_in, const int* in_sizes, int n_in,
                              void* d_out, int out_size)
{
    const float* x          = (const float*)d_in[0];
    const float* in_proj_w  = (const float*)d_in[1];
    const float* conv_w     = (const float*)d_in[2];
    const float* conv_b     = (const float*)d_in[3];
    const float* x_proj_w   = (const float*)d_in[4];
    const float* dt_proj_w  = (const float*)d_in[5];
    const float* dt_proj_b  = (const float*)d_in[6];
    const float* A_log      = (const float*)d_in[7];
    const float* Dp         = (const float*)d_in[8];
    const float* out_proj_w = (const float*)d_in[9];
    const float* lin1_w     = (const float*)d_in[10];
    const float* lin1_b     = (const float*)d_in[11];
    const float* lin2_w     = (const float*)d_in[12];
    const float* lin2_b     = (const float*)d_in[13];
    float* out = (float*)d_out;

    float *p_xz, *p_uc, *p_xdbl, *p_dt, *p_y, *p_y2, *p_h;
    cudaGetSymbolAddress((void**)&p_xz,   g_xz);
    cudaGetSymbolAddress((void**)&p_uc,   g_uc);
    cudaGetSymbolAddress((void**)&p_xdbl, g_xdbl);
    cudaGetSymbolAddress((void**)&p_dt,   g_dt);
    cudaGetSymbolAddress((void**)&p_y,    g_y);
    cudaGetSymbolAddress((void**)&p_y2,   g_y2);
    cudaGetSymbolAddress((void**)&p_h,    g_hh);

    dim3 blk(256);

    // 1) xz = x @ in_proj_w^T
    gemm_bf16x3<0><<<dim3((2 * EI) / 128, MROWS / 128), blk>>>(
        x, DMODEL, in_proj_w, (const float*)0, p_xz, 2 * EI, DMODEL);

    // 2) causal depthwise conv + silu -> g_uc
    conv_silu_kernel<<<(unsigned)(((size_t)MROWS * EI) / 256), 256>>>(conv_w, conv_b);

    // 3) x_dbl = uc @ x_proj_w^T
    gemm_bf16x3<0><<<dim3((XDBLW + 127) / 128, MROWS / 128), blk>>>(
        p_uc, EI, x_proj_w, (const float*)0, p_xdbl, XDBLW, EI);

    // 4) dt = softplus(dt_raw @ dt_proj_w^T + b)
    gemm_bf16x3<3><<<dim3(EI / 128, MROWS / 128), blk>>>(
        p_xdbl, XDBLW, dt_proj_w, dt_proj_b, p_dt, EI, DTRANK);

    // 5) selective scan -> g_y
    scan_kernel<<<(BB * EI) / 16, 256>>>(A_log, Dp);

    // 6) y2 = y @ out_proj_w^T
    gemm_bf16x3<0><<<dim3(DMODEL / 128, MROWS / 128), blk>>>(
        p_y, EI, out_proj_w, (const float*)0, p_y2, DMODEL, EI);

    // 7) h = relu(y2 @ lin1_w^T + b)
    gemm_bf16x3<1><<<dim3(DFF / 128, MROWS / 128), blk>>>(
        p_y2, DMODEL, lin1_w, lin1_b, p_h, DFF, DMODEL);

    // 8) out = h @ lin2_w^T + b
    gemm_bf16x3<2><<<dim3(DMODEL / 128, MROWS / 128), blk>>>(
        p_h, DFF, lin2_w, lin2_b, out, DMODEL, DFF);
}

// round 6
// speedup vs baseline: 1.4518x; 1.0880x over previous
#include <cuda_runtime.h>
#include <cuda_bf16.h>
#include <stdint.h>
#include <math.h>

// Problem constants
#define BB     4
#define LL     2048
#define DMODEL 1024
#define EI     2048      // d_inner
#define NSTATE 16
#define DCONV  4
#define DTRANK 64
#define DFF    4096
#define MROWS  (BB*LL)           // 8192
#define XDBLW  (DTRANK+2*NSTATE) // 96

typedef __nv_bfloat16 bf16;

// -------- fp32 scratch --------
__device__ float g_xz  [(size_t)MROWS*2*EI];
__device__ float g_uc  [(size_t)MROWS*EI];
__device__ float g_xdbl[(size_t)MROWS*XDBLW];
__device__ float g_dt  [(size_t)MROWS*EI];
// -------- bf16 triple-K (split) scratch: activations (hi,lo,hi) --------
__device__ bf16 g_xs   [(size_t)MROWS*3*DMODEL];
__device__ bf16 g_ucs  [(size_t)MROWS*3*EI];
__device__ bf16 g_xdbls[(size_t)MROWS*3*DTRANK];
__device__ bf16 g_ys   [(size_t)MROWS*3*EI];
__device__ bf16 g_y2s  [(size_t)MROWS*3*DMODEL];
__device__ bf16 g_hs   [(size_t)MROWS*3*DFF];
// -------- weight splits (whi,whi,wlo) --------
__device__ bf16 g_win [(size_t)(2*EI)*3*DMODEL];
__device__ bf16 g_wxp [(size_t)XDBLW*3*EI];
__device__ bf16 g_wdt [(size_t)EI*3*DTRANK];
__device__ bf16 g_wout[(size_t)DMODEL*3*EI];
__device__ bf16 g_wl1 [(size_t)DFF*3*DMODEL];
__device__ bf16 g_wl2 [(size_t)DMODEL*3*DFF];

// ---------------- PTX helpers ----------------
__device__ __forceinline__ void ldsm4(unsigned& r0, unsigned& r1, unsigned& r2, unsigned& r3,
                                      const void* p)
{
    unsigned a = (unsigned)__cvta_generic_to_shared(p);
    asm volatile("ldmatrix.sync.aligned.m8n8.x4.shared.b16 {%0,%1,%2,%3}, [%4];\n"
                 : "=r"(r0), "=r"(r1), "=r"(r2), "=r"(r3) : "r"(a));
}

__device__ __forceinline__ void mma16816(float* d, const unsigned* a, const unsigned* b)
{
    asm volatile(
        "mma.sync.aligned.m16n8k16.row.col.f32.bf16.bf16.f32 "
        "{%0,%1,%2,%3}, {%4,%5,%6,%7}, {%8,%9}, {%0,%1,%2,%3};\n"
        : "+f"(d[0]), "+f"(d[1]), "+f"(d[2]), "+f"(d[3])
        : "r"(a[0]), "r"(a[1]), "r"(a[2]), "r"(a[3]), "r"(b[0]), "r"(b[1]));
}

__device__ __forceinline__ void cpa16(void* s, const void* g)
{
    unsigned sa = (unsigned)__cvta_generic_to_shared(s);
    asm volatile("cp.async.cg.shared.global [%0], [%1], 16;\n" :: "r"(sa), "l"(g));
}
__device__ __forceinline__ void cpa16z(void* s, const void* g, bool pred)
{
    unsigned sa = (unsigned)__cvta_generic_to_shared(s);
    int sz = pred ? 16 : 0;
    asm volatile("cp.async.cg.shared.global [%0], [%1], 16, %2;\n" :: "r"(sa), "l"(g), "r"(sz));
}
__device__ __forceinline__ void cp_commit() { asm volatile("cp.async.commit_group;\n"); }
__device__ __forceinline__ void cp_wait1()  { asm volatile("cp.async.wait_group 1;\n"); }
__device__ __forceinline__ void cp_wait0()  { asm volatile("cp.async.wait_group 0;\n"); }

template<int EPI>
__device__ __forceinline__ float epi_apply(float v, const float* bias, int n)
{
    if (EPI == 1)      v = fmaxf(v + bias[n], 0.f);
    else if (EPI == 2) v = v + bias[n];
    else if (EPI == 3) { v += bias[n]; v = (v > 20.f) ? v : log1pf(expf(v)); }
    return v;
}

// ---------------- split kernels ----------------
// activations: (hi, lo, hi)
__global__ void split_a_kernel(const float* __restrict__ A, bf16* __restrict__ AS,
                               size_t total)
{
    size_t idx = (size_t)blockIdx.x * blockDim.x + threadIdx.x;
    if (idx >= total) return;
    float v = A[idx];
    bf16 h = __float2bfloat16(v);
    bf16 l = __float2bfloat16(v - __bfloat162float(h));
    size_t o = idx * 3;
    AS[o] = h; AS[o + 1] = l; AS[o + 2] = h;
}
// weights: (hi, hi, lo)
__global__ void split_w_kernel(const float* __restrict__ W, bf16* __restrict__ WS,
                               size_t total)
{
    size_t idx = (size_t)blockIdx.x * blockDim.x + threadIdx.x;
    if (idx >= total) return;
    float v = W[idx];
    bf16 h = __float2bfloat16(v);
    bf16 l = __float2bfloat16(v - __bfloat162float(h));
    size_t o = idx * 3;
    WS[o] = h; WS[o + 1] = h; WS[o + 2] = l;
}

// ------------- pipelined bf16 GEMM over pre-split K': C = A[M,K'] * W[N,K']^T -------------
// EPI: 0=none, 1=bias+relu, 2=bias, 3=bias+softplus
// C (fp32, may be null), CS (bf16 triple (hi,lo,hi), may be null, width Nsplit)
#define SKW 40
template<int EPI>
__global__ void __launch_bounds__(256, 2)
gemm_bf16(const bf16* __restrict__ A, const bf16* __restrict__ W,
          const float* __restrict__ bias,
          float* __restrict__ C, bf16* __restrict__ CS,
          int Nv, int Nsplit, int Kp)
{
    __shared__ bf16 sA[2][128][SKW];
    __shared__ bf16 sW[2][128][SKW];

    const int tid  = threadIdx.x;
    const int lane = tid & 31;
    const int w    = tid >> 5;
    const int bm   = blockIdx.y * 128;
    const int bn   = blockIdx.x * 128;
    const int wm   = (w >> 1) * 32;
    const int wn   = (w & 1) * 64;

    const int lrow = tid >> 1;            // 0..127
    const int lc16 = (tid & 1) * 16;      // elem col offset {0,16}
    const bool wok = (bn + lrow) < Nv;

    const bf16* gA = A + (size_t)(bm + lrow) * Kp + lc16;
    const bf16* gW = W + (size_t)(wok ? (bn + lrow) : bn) * Kp + lc16;

    const int a_r = lane & 15, a_c = (lane >> 4) * 8;
    const int b_r = (lane & 7) + ((lane >> 4) << 3), b_c = ((lane >> 3) & 1) * 8;

    float acc[2][8][4];
#pragma unroll
    for (int i = 0; i < 2; i++)
#pragma unroll
        for (int j = 0; j < 8; j++)
#pragma unroll
            for (int q = 0; q < 4; q++) acc[i][j][q] = 0.f;

    const int nk = Kp >> 5;

    // preload stage 0
    cpa16(&sA[0][lrow][lc16],     gA);
    cpa16(&sA[0][lrow][lc16 + 8], gA + 8);
    cpa16z(&sW[0][lrow][lc16],     gW,     wok);
    cpa16z(&sW[0][lrow][lc16 + 8], gW + 8, wok);
    cp_commit();

    for (int kb = 0; kb < nk; kb++) {
        const int buf = kb & 1;
        if (kb + 1 < nk) {
            const bf16* pa = gA + (size_t)(kb + 1) * 32;
            const bf16* pw = gW + (size_t)(kb + 1) * 32;
            const int nb = (kb + 1) & 1;
            cpa16(&sA[nb][lrow][lc16],     pa);
            cpa16(&sA[nb][lrow][lc16 + 8], pa + 8);
            cpa16z(&sW[nb][lrow][lc16],     pw,     wok);
            cpa16z(&sW[nb][lrow][lc16 + 8], pw + 8, wok);
            cp_commit();
            cp_wait1();
        } else {
            cp_wait0();
        }
        __syncthreads();

#pragma unroll
        for (int kk = 0; kk < 32; kk += 16) {
            unsigned af[2][4];
#pragma unroll
            for (int mi = 0; mi < 2; mi++)
                ldsm4(af[mi][0], af[mi][1], af[mi][2], af[mi][3],
                      &sA[buf][wm + mi * 16 + a_r][kk + a_c]);
#pragma unroll
            for (int p = 0; p < 4; p++) {
                unsigned bfr[4];
                ldsm4(bfr[0], bfr[1], bfr[2], bfr[3],
                      &sW[buf][wn + p * 16 + b_r][kk + b_c]);
#pragma unroll
                for (int mi = 0; mi < 2; mi++) {
                    mma16816(acc[mi][2 * p],     af[mi], bfr);
                    mma16816(acc[mi][2 * p + 1], af[mi], bfr + 2);
                }
            }
        }
        __syncthreads();
    }

    // ---- epilogue ----
    const int grp = lane >> 2;
    const int tq  = lane & 3;
#pragma unroll
    for (int mi = 0; mi < 2; mi++) {
#pragma unroll
        for (int nj = 0; nj < 8; nj++) {
            float* d = acc[mi][nj];
            int r0 = bm + wm + mi * 16 + grp;
            int c  = bn + wn + nj * 8 + tq * 2;
#pragma unroll
            for (int q = 0; q < 4; q++) {
                int r = r0 + (q >> 1) * 8;
                int cc = c + (q & 1);
                if (cc < Nv) {
                    float v = epi_apply<EPI>(d[q], bias, cc);
                    if (C) C[(size_t)r * Nv + cc] = v;
                    if (CS && cc < Nsplit) {
                        bf16 h = __float2bfloat16(v);
                        bf16 l = __float2bfloat16(v - __bfloat162float(h));
                        size_t o = (size_t)r * 3 * Nsplit + 3 * cc;
                        CS[o] = h; CS[o + 1] = l; CS[o + 2] = h;
                    }
                }
            }
        }
    }
}

// ---------------- causal depthwise conv (k=4) + bias + silu ----------------
__global__ void conv_silu_kernel(const float* __restrict__ conv_w,
                                 const float* __restrict__ conv_b)
{
    size_t idx = (size_t)blockIdx.x * blockDim.x + threadIdx.x;
    if (idx >= (size_t)MROWS * EI) return;
    int e = (int)(idx % EI);
    int row = (int)(idx / EI);
    int l = row % LL;
    float s = conv_b[e];
#pragma unroll
    for (int j = 0; j < DCONV; j++) {
        int ls = l - (DCONV - 1) + j;
        if (ls >= 0) {
            int rs = row - (DCONV - 1) + j;
            s += conv_w[e * DCONV + j] * g_xz[(size_t)rs * (2 * EI) + e];
        }
    }
    float sig = 1.f / (1.f + expf(-s));
    float v = s * sig;
    g_uc[idx] = v;
    bf16 h = __float2bfloat16(v);
    bf16 lo = __float2bfloat16(v - __bfloat162float(h));
    size_t o = (size_t)row * 3 * EI + 3 * e;
    g_ucs[o] = h; g_ucs[o + 1] = lo; g_ucs[o + 2] = h;
}

// ---------------- selective scan: 16 lanes per (b,e) channel ----------------
__global__ void scan_kernel(const float* __restrict__ A_log,
                            const float* __restrict__ Dp)
{
    int gid = blockIdx.x * (blockDim.x >> 4) + (threadIdx.x >> 4);
    int n = threadIdx.x & 15;
    int b = gid >> 11;
    int e = gid & (EI - 1);

    float Aen = -expf(A_log[e * NSTATE + n]);
    float Dv = Dp[e];
    float h = 0.f;
    size_t row = (size_t)b * LL;
    for (int l = 0; l < LL; l++, row++) {
        float dtv = g_dt[row * EI + e];
        float uv  = g_uc[row * EI + e];
        const float* pbc = g_xdbl + row * XDBLW;
        float Bt = pbc[DTRANK + n];
        float Ct = pbc[DTRANK + NSTATE + n];
        h = expf(dtv * Aen) * h + dtv * uv * Bt;
        float p = h * Ct;
        p += __shfl_xor_sync(0xffffffffu, p, 8);
        p += __shfl_xor_sync(0xffffffffu, p, 4);
        p += __shfl_xor_sync(0xffffffffu, p, 2);
        p += __shfl_xor_sync(0xffffffffu, p, 1);
        if (n == 0) {
            float zv = g_xz[row * (2 * EI) + EI + e];
            float yv = (p + uv * Dv) * (zv / (1.f + expf(-zv)));
            bf16 hh = __float2bfloat16(yv);
            bf16 ll = __float2bfloat16(yv - __bfloat162float(hh));
            size_t o = row * 3 * EI + 3 * e;
            g_ys[o] = hh; g_ys[o + 1] = ll; g_ys[o + 2] = hh;
        }
    }
}

// ---------------- host launch ----------------
extern "C" void kernel_launch(void* const* d_in, const int* in_sizes, int n_in,
                              void* d_out, int out_size)
{
    const float* x          = (const float*)d_in[0];
    const float* in_proj_w  = (const float*)d_in[1];
    const float* conv_w     = (const float*)d_in[2];
    const float* conv_b     = (const float*)d_in[3];
    const float* x_proj_w   = (const float*)d_in[4];
    const float* dt_proj_w  = (const float*)d_in[5];
    const float* dt_proj_b  = (const float*)d_in[6];
    const float* A_log      = (const float*)d_in[7];
    const float* Dp         = (const float*)d_in[8];
    const float* out_proj_w = (const float*)d_in[9];
    const float* lin1_w     = (const float*)d_in[10];
    const float* lin1_b     = (const float*)d_in[11];
    const float* lin2_w     = (const float*)d_in[12];
    const float* lin2_b     = (const float*)d_in[13];
    float* out = (float*)d_out;

    float *p_xz, *p_xdbl, *p_dt;
    bf16 *p_xs, *p_ucs, *p_xdbls, *p_ys, *p_y2s, *p_hs;
    bf16 *p_win, *p_wxp, *p_wdt, *p_wout, *p_wl1, *p_wl2;
    cudaGetSymbolAddress((void**)&p_xz,    g_xz);
    cudaGetSymbolAddress((void**)&p_xdbl,  g_xdbl);
    cudaGetSymbolAddress((void**)&p_dt,    g_dt);
    cudaGetSymbolAddress((void**)&p_xs,    g_xs);
    cudaGetSymbolAddress((void**)&p_ucs,   g_ucs);
    cudaGetSymbolAddress((void**)&p_xdbls, g_xdbls);
    cudaGetSymbolAddress((void**)&p_ys,    g_ys);
    cudaGetSymbolAddress((void**)&p_y2s,   g_y2s);
    cudaGetSymbolAddress((void**)&p_hs,    g_hs);
    cudaGetSymbolAddress((void**)&p_win,   g_win);
    cudaGetSymbolAddress((void**)&p_wxp,   g_wxp);
    cudaGetSymbolAddress((void**)&p_wdt,   g_wdt);
    cudaGetSymbolAddress((void**)&p_wout,  g_wout);
    cudaGetSymbolAddress((void**)&p_wl1,   g_wl1);
    cudaGetSymbolAddress((void**)&p_wl2,   g_wl2);

    dim3 blk(256);
    const int GY = MROWS / 128;   // 64

    // ---- splits ----
    {
        size_t t;
        t = (size_t)MROWS * DMODEL;
        split_a_kernel<<<(unsigned)((t + 255) / 256), 256>>>(x, p_xs, t);
        t = (size_t)(2 * EI) * DMODEL;
        split_w_kernel<<<(unsigned)((t + 255) / 256), 256>>>(in_proj_w, p_win, t);
        t = (size_t)XDBLW * EI;
        split_w_kernel<<<(unsigned)((t + 255) / 256), 256>>>(x_proj_w, p_wxp, t);
        t = (size_t)EI * DTRANK;
        split_w_kernel<<<(unsigned)((t + 255) / 256), 256>>>(dt_proj_w, p_wdt, t);
        t = (size_t)DMODEL * EI;
        split_w_kernel<<<(unsigned)((t + 255) / 256), 256>>>(out_proj_w, p_wout, t);
        t = (size_t)DFF * DMODEL;
        split_w_kernel<<<(unsigned)((t + 255) / 256), 256>>>(lin1_w, p_wl1, t);
        t = (size_t)DMODEL * DFF;
        split_w_kernel<<<(unsigned)((t + 255) / 256), 256>>>(lin2_w, p_wl2, t);
    }

    // 1) xz = x @ in_proj_w^T   -> fp32 g_xz
    gemm_bf16<0><<<dim3((2 * EI) / 128, GY), blk>>>(
        p_xs, p_win, (const float*)0, p_xz, (bf16*)0, 2 * EI, 0, 3 * DMODEL);

    // 2) conv + silu -> g_uc fp32 + g_ucs split
    conv_silu_kernel<<<(unsigned)(((size_t)MROWS * EI) / 256), 256>>>(conv_w, conv_b);

    // 3) x_dbl = uc @ x_proj_w^T -> fp32 g_xdbl (96 cols) + split of first 64 cols
    gemm_bf16<0><<<dim3(1, GY), blk>>>(
        p_ucs, p_wxp, (const float*)0, p_xdbl, p_xdbls, XDBLW, DTRANK, 3 * EI);

    // 4) dt = softplus(dt_raw @ dt_proj_w^T + b) -> fp32 g_dt
    gemm_bf16<3><<<dim3(EI / 128, GY), blk>>>(
        p_xdbls, p_wdt, dt_proj_b, p_dt, (bf16*)0, EI, 0, 3 * DTRANK);

    // 5) selective scan -> g_ys split
    scan_kernel<<<(BB * EI) / 16, 256>>>(A_log, Dp);

    // 6) y2 = y @ out_proj_w^T -> g_y2s split only
    gemm_bf16<0><<<dim3(DMODEL / 128, GY), blk>>>(
        p_ys, p_wout, (const float*)0, (float*)0, p_y2s, DMODEL, DMODEL, 3 * EI);

    // 7) h = relu(y2 @ lin1_w^T + b) -> g_hs split only
    gemm_bf16<1><<<dim3(DFF / 128, GY), blk>>>(
        p_y2s, p_wl1, lin1_b, (float*)0, p_hs, DFF, DFF, 3 * DMODEL);

    // 8) out = h @ lin2_w^T + b -> fp32 out
    gemm_bf16<2><<<dim3(DMODEL / 128, GY), blk>>>(
        p_hs, p_wl2, lin2_b, out, (bf16*)0, DMODEL, 0, 3 * DFF);
}